// round 11
// baseline (speedup 1.0000x reference)
#include <cuda_runtime.h>
#include <cstdint>

// 3x3 conv, stride 1, pad 1, single channel, X: (32, 1024, 1024) fp32.
// Bulk-async + high occupancy: each CTA computes a 4-row x 1024-col band.
// The 6 input rows (24KB, contiguous) arrive via ONE cp.async.bulk into
// static smem (mbarrier). 24KB smem -> 7 CTAs/SM (~87% occ): many CTAs per
// SM hide each other's copy waits, keeping the DRAM queue full. Halo cols
// via warp shuffle (no smem bank conflicts). __stcs float4 stores.

#define IMG_W 1024
#define IMG_H 1024
#define ROWS_CTA 4
#define SM_ROWS (ROWS_CTA + 2)

__device__ __forceinline__ uint32_t smem_u32(const void* p) {
    uint32_t a;
    asm("{ .reg .u64 t; cvta.to.shared.u64 t, %1; cvt.u32.u64 %0, t; }"
        : "=r"(a) : "l"(p));
    return a;
}

__global__ __launch_bounds__(256, 7) void conv3x3_kernel(
    const float* __restrict__ X,
    const float* __restrict__ Wt,
    float* __restrict__ Y)
{
    __shared__ __align__(128) float sm[SM_ROWS * IMG_W];
    __shared__ __align__(8)  unsigned long long mbar;

    const int tid   = threadIdx.x;
    const int lane  = tid & 31;
    const int bx    = blockIdx.x;
    const int batch = bx >> 8;            // / 256 bands
    const int band  = bx & 255;
    const int r0    = band << 2;          // first output row
    const int c0    = tid << 2;           // 4 cols per thread (covers 1024)

    const size_t plane = (size_t)IMG_W * IMG_H;
    const float* Xb = X + (size_t)batch * plane;
    float*       Yb = Y + (size_t)batch * plane;

    const uint32_t mbar_a = smem_u32(&mbar);
    const uint32_t sm_a   = smem_u32(sm);

    if (tid == 0) {
        asm volatile("mbarrier.init.shared.b64 [%0], 1;" :: "r"(mbar_a) : "memory");
    }
    __syncthreads();

    // One contiguous bulk copy: gmem rows [gstart, gend] -> smem.
    const int r_first = r0 - 1;
    const int gstart  = r_first < 0 ? 0 : r_first;
    const int gend_i  = r0 + ROWS_CTA;                 // halo row below
    const int gend    = gend_i > (IMG_H - 1) ? (IMG_H - 1) : gend_i;
    const uint32_t nbytes = (uint32_t)(gend - gstart + 1) * IMG_W * 4u;
    const uint32_t dst    = sm_a + (uint32_t)(gstart - r_first) * IMG_W * 4u;
    const float*   src    = Xb + (size_t)gstart * IMG_W;

    if (tid == 0) {
        asm volatile("mbarrier.arrive.expect_tx.shared.b64 _, [%0], %1;"
                     :: "r"(mbar_a), "r"(nbytes) : "memory");
        asm volatile(
            "cp.async.bulk.shared::cta.global.mbarrier::complete_tx::bytes "
            "[%0], [%1], %2, [%3];"
            :: "r"(dst), "l"(src), "r"(nbytes), "r"(mbar_a) : "memory");
    }

    // Zero pad rows (never written by the copy) while the copy is in flight.
    if (r_first < 0) {
        float4 z = make_float4(0.f, 0.f, 0.f, 0.f);
        *reinterpret_cast<float4*>(&sm[c0]) = z;
    }
    if (gend_i > IMG_H - 1) {
        float4 z = make_float4(0.f, 0.f, 0.f, 0.f);
        *reinterpret_cast<float4*>(&sm[(SM_ROWS - 1) * IMG_W + c0]) = z;
    }

    // Weights (L2-cached broadcast) while the copy is in flight.
    float w[9];
#pragma unroll
    for (int i = 0; i < 9; i++) w[i] = __ldg(Wt + i);

    // Wait for the bulk copy (phase 0), then sync so pad zeros are visible.
    asm volatile(
        "{\n\t"
        ".reg .pred P;\n\t"
        "WAIT_%=:\n\t"
        "mbarrier.try_wait.parity.acquire.cta.shared::cta.b64 P, [%0], 0;\n\t"
        "@!P bra WAIT_%=;\n\t"
        "}"
        :: "r"(mbar_a) : "memory");
    __syncthreads();

    // Per output row: read 3 smem rows (float4 + shuffle halos), fma, store.
#pragma unroll
    for (int i = 0; i < ROWS_CTA; i++) {
        float acc[4] = {0.f, 0.f, 0.f, 0.f};
#pragma unroll
        for (int ky = 0; ky < 3; ky++) {
            const float* rp = &sm[(i + ky) * IMG_W];
            const float4 v = *reinterpret_cast<const float4*>(rp + c0);
            float row[6];
            row[1] = v.x; row[2] = v.y; row[3] = v.z; row[4] = v.w;
            float left  = __shfl_up_sync(0xFFFFFFFFu,  v.w, 1);
            float right = __shfl_down_sync(0xFFFFFFFFu, v.x, 1);
            if (lane == 0)  left  = (c0 > 0)          ? rp[c0 - 1] : 0.0f;
            if (lane == 31) right = (c0 + 4 < IMG_W)  ? rp[c0 + 4] : 0.0f;
            row[0] = left;
            row[5] = right;
#pragma unroll
            for (int j = 0; j < 4; j++) {
                acc[j] = fmaf(w[ky * 3 + 0], row[j],
                         fmaf(w[ky * 3 + 1], row[j + 1],
                         fmaf(w[ky * 3 + 2], row[j + 2], acc[j])));
            }
        }
        float4 o;
        o.x = acc[0]; o.y = acc[1]; o.z = acc[2]; o.w = acc[3];
        __stcs(reinterpret_cast<float4*>(Yb + (size_t)(r0 + i) * IMG_W + c0), o);
    }
}

extern "C" void kernel_launch(void* const* d_in, const int* in_sizes, int n_in,
                              void* d_out, int out_size)
{
    const float* X  = (const float*)d_in[0];   // (32, 1024, 1024) fp32
    const float* Wt = (const float*)d_in[1];   // (3, 3) fp32
    float* Y        = (float*)d_out;           // (32, 1024, 1024) fp32

    const int grid = 32 * 256;                 // batches * 4-row bands
    conv3x3_kernel<<<grid, 256>>>(X, Wt, Y);
}

// round 12
// speedup vs baseline: 1.2892x; 1.2892x over previous
#include <cuda_runtime.h>
#include <cstdint>

// 3x3 conv, stride 1, pad 1, single channel, X: (32, 1024, 1024) fp32.
// R10 structure resized: each CTA computes a 4-row x 1024-col band; the 6
// input rows (24KB contiguous) arrive via ONE cp.async.bulk into static
// smem (mbarrier). 24KB -> 6 CTAs/SM (75% occ) so CTAs hide each other's
// copy waits; grid 8192 gives a smooth ~9-wave schedule. Compute is the
// proven one-touch rolling 3-row register window (low instructions/byte);
// __stcs float4 stores.

#define IMG_W 1024
#define IMG_H 1024
#define ROWS_CTA 4
#define SM_ROWS (ROWS_CTA + 2)

__device__ __forceinline__ uint32_t smem_u32(const void* p) {
    uint32_t a;
    asm("{ .reg .u64 t; cvta.to.shared.u64 t, %1; cvt.u32.u64 %0, t; }"
        : "=r"(a) : "l"(p));
    return a;
}

__global__ __launch_bounds__(256, 6) void conv3x3_kernel(
    const float* __restrict__ X,
    const float* __restrict__ Wt,
    float* __restrict__ Y)
{
    __shared__ __align__(128) float sm[SM_ROWS * IMG_W];
    __shared__ __align__(8)  unsigned long long mbar;

    const int tid   = threadIdx.x;
    const int bx    = blockIdx.x;
    const int batch = bx >> 8;            // / 256 bands
    const int band  = bx & 255;
    const int r0    = band << 2;          // first output row
    const int c0    = tid << 2;           // 4 cols per thread (covers 1024)

    const size_t plane = (size_t)IMG_W * IMG_H;
    const float* Xb = X + (size_t)batch * plane;
    float*       Yb = Y + (size_t)batch * plane;

    const uint32_t mbar_a = smem_u32(&mbar);
    const uint32_t sm_a   = smem_u32(sm);

    if (tid == 0) {
        asm volatile("mbarrier.init.shared.b64 [%0], 1;" :: "r"(mbar_a) : "memory");
    }
    __syncthreads();

    // One contiguous bulk copy: gmem rows [gstart, gend] -> smem rows
    // starting at (gstart - (r0-1)).
    const int r_first = r0 - 1;
    const int gstart  = r_first < 0 ? 0 : r_first;
    const int gend_i  = r0 + ROWS_CTA;                 // halo row below
    const int gend    = gend_i > (IMG_H - 1) ? (IMG_H - 1) : gend_i;
    const uint32_t nbytes = (uint32_t)(gend - gstart + 1) * IMG_W * 4u;
    const uint32_t dst    = sm_a + (uint32_t)(gstart - r_first) * IMG_W * 4u;
    const float*   src    = Xb + (size_t)gstart * IMG_W;

    if (tid == 0) {
        asm volatile("mbarrier.arrive.expect_tx.shared.b64 _, [%0], %1;"
                     :: "r"(mbar_a), "r"(nbytes) : "memory");
        asm volatile(
            "cp.async.bulk.shared::cta.global.mbarrier::complete_tx::bytes "
            "[%0], [%1], %2, [%3];"
            :: "r"(dst), "l"(src), "r"(nbytes), "r"(mbar_a) : "memory");
    }

    // Zero pad rows (never written by the copy) while the copy is in flight.
    if (r_first < 0) {
        float4 z = make_float4(0.f, 0.f, 0.f, 0.f);
        *reinterpret_cast<float4*>(&sm[c0]) = z;
    }
    if (gend_i > IMG_H - 1) {
        float4 z = make_float4(0.f, 0.f, 0.f, 0.f);
        *reinterpret_cast<float4*>(&sm[(SM_ROWS - 1) * IMG_W + c0]) = z;
    }

    // Weights (L2-cached broadcast) while the copy is in flight.
    float w[9];
#pragma unroll
    for (int i = 0; i < 9; i++) w[i] = __ldg(Wt + i);

    // Wait for the bulk copy (phase 0), then sync so pad zeros are visible.
    asm volatile(
        "{\n\t"
        ".reg .pred P;\n\t"
        "WAIT_%=:\n\t"
        "mbarrier.try_wait.parity.acquire.cta.shared::cta.b64 P, [%0], 0;\n\t"
        "@!P bra WAIT_%=;\n\t"
        "}"
        :: "r"(mbar_a) : "memory");
    __syncthreads();

    // Rolling 3-row register window; smem row k = input row r0 + k - 1.
    // Each smem row is read exactly once per thread.
    float b[3][6];

#define LOAD_SMROW(dstbuf, k)                                                 \
    do {                                                                      \
        const float* rp = &sm[(k) * IMG_W];                                   \
        const float4 v = *reinterpret_cast<const float4*>(rp + c0);           \
        (dstbuf)[1] = v.x; (dstbuf)[2] = v.y;                                 \
        (dstbuf)[3] = v.z; (dstbuf)[4] = v.w;                                 \
        (dstbuf)[0] = (c0 > 0)           ? rp[c0 - 1] : 0.0f;                 \
        (dstbuf)[5] = (c0 + 4 < IMG_W)   ? rp[c0 + 4] : 0.0f;                 \
    } while (0)

    LOAD_SMROW(b[0], 0);
    LOAD_SMROW(b[1], 1);

#pragma unroll
    for (int i = 0; i < ROWS_CTA; i++) {
        LOAD_SMROW(b[(i + 2) % 3], i + 2);

        const float* t0 = b[i % 3];         // input row r0+i-1  (ky=0)
        const float* t1 = b[(i + 1) % 3];   // input row r0+i    (ky=1)
        const float* t2 = b[(i + 2) % 3];   // input row r0+i+1  (ky=2)

        float4 o;
        float acc[4];
#pragma unroll
        for (int j = 0; j < 4; j++) {
            float a;
            a = fmaf(w[0], t0[j], fmaf(w[1], t0[j + 1], w[2] * t0[j + 2]));
            a = fmaf(w[3], t1[j], fmaf(w[4], t1[j + 1], fmaf(w[5], t1[j + 2], a)));
            a = fmaf(w[6], t2[j], fmaf(w[7], t2[j + 1], fmaf(w[8], t2[j + 2], a)));
            acc[j] = a;
        }
        o.x = acc[0]; o.y = acc[1]; o.z = acc[2]; o.w = acc[3];
        __stcs(reinterpret_cast<float4*>(Yb + (size_t)(r0 + i) * IMG_W + c0), o);
    }
#undef LOAD_SMROW
}

extern "C" void kernel_launch(void* const* d_in, const int* in_sizes, int n_in,
                              void* d_out, int out_size)
{
    const float* X  = (const float*)d_in[0];   // (32, 1024, 1024) fp32
    const float* Wt = (const float*)d_in[1];   // (3, 3) fp32
    float* Y        = (float*)d_out;           // (32, 1024, 1024) fp32

    const int grid = 32 * 256;                 // batches * 4-row bands
    conv3x3_kernel<<<grid, 256>>>(X, Wt, Y);
}